// round 2
// baseline (speedup 1.0000x reference)
#include <cuda_runtime.h>
#include <cstdint>
#include <cstddef>
#include <math.h>

// ---------------------------------------------------------------------------
// GLN_56006373539841: 3-layer Gated Linear Network.
//   B=4096, D_IN=1024, D_LAT=2048, D_OUT=1024, SHATTER=3, NC=8
// Round 1: fp32 SGEMM everywhere + fp64 "rescue" of near-threshold context
// scores (sign decisions) to eliminate context bit flips vs the reference.
// ---------------------------------------------------------------------------

#define BM 128
#define BN 128
#define BK 16

// Rescue band: any |score - T| below this is recomputed in fp64.
// Must exceed our fp32 accumulation error (~1e-4 abs) with wide margin.
#define RESCUE_TAU 2e-3f

// Scratch (device globals: allocation-free per harness rules)
__device__ float         g_S   [4096u * 6144u];   // context scores, reused per layer
__device__ float         g_h0  [4096u * 2048u];
__device__ float         g_h1  [4096u * 2048u];
__device__ unsigned char g_ctx0[4096u * 2048u];
__device__ unsigned char g_ctx1[4096u * 2048u];
__device__ unsigned char g_ctx2[4096u * 1024u];

// MODE 0: C[M,N] dense store.  MODE 1: select-write out[M, N/8] with ctx+bias.
template <int MODE>
__global__ __launch_bounds__(256, 2)
void gln_sgemm(const float* __restrict__ A,   // [M, K] row-major
               const float* __restrict__ B,   // [N, K] row-major (B^T applied)
               float* __restrict__ C,         // MODE0: [M,N]; MODE1: [M, N/8]
               const unsigned char* __restrict__ ctx, // MODE1: [M, N/8]
               const float* __restrict__ bias,        // MODE1: [N] or null
               int M, int N, int K)
{
    __shared__ float As[BK][BM];
    __shared__ float Bs[BK][BN];

    const int tid  = threadIdx.x;
    const int tx   = tid & 15;   // 0..15  (N micro-dim)
    const int ty   = tid >> 4;   // 0..15  (M micro-dim)
    const int row0 = blockIdx.x * BM;   // M-dim on x: consecutive blocks share W tile (L2)
    const int col0 = blockIdx.y * BN;

    float acc[8][8];
#pragma unroll
    for (int i = 0; i < 8; i++)
#pragma unroll
        for (int j = 0; j < 8; j++) acc[i][j] = 0.0f;

    const float* Ab = A + (size_t)row0 * K;
    const float* Bb = B + (size_t)col0 * K;

    for (int k0 = 0; k0 < K; k0 += BK) {
        // Load 128x16 A and B tiles: 512 float4 slots each, 2 per thread.
#pragma unroll
        for (int i = 0; i < 2; i++) {
            int slot = tid + i * 256;        // 0..511
            int r    = slot >> 2;            // 0..127
            int c4   = (slot & 3) << 2;      // 0,4,8,12
            float4 va = *(const float4*)(Ab + (size_t)r * K + k0 + c4);
            As[c4 + 0][r] = va.x; As[c4 + 1][r] = va.y;
            As[c4 + 2][r] = va.z; As[c4 + 3][r] = va.w;
            float4 vb = *(const float4*)(Bb + (size_t)r * K + k0 + c4);
            Bs[c4 + 0][r] = vb.x; Bs[c4 + 1][r] = vb.y;
            Bs[c4 + 2][r] = vb.z; Bs[c4 + 3][r] = vb.w;
        }
        __syncthreads();

#pragma unroll
        for (int k = 0; k < BK; k++) {
            float a[8], b[8];
            *(float4*)&a[0] = *(const float4*)&As[k][ty * 4];
            *(float4*)&a[4] = *(const float4*)&As[k][64 + ty * 4];
            *(float4*)&b[0] = *(const float4*)&Bs[k][tx * 4];
            *(float4*)&b[4] = *(const float4*)&Bs[k][64 + tx * 4];
#pragma unroll
            for (int i = 0; i < 8; i++)
#pragma unroll
                for (int j = 0; j < 8; j++)
                    acc[i][j] = fmaf(a[i], b[j], acc[i][j]);
        }
        __syncthreads();
    }

    if (MODE == 0) {
        // Dense store (context scores)
#pragma unroll
        for (int i = 0; i < 8; i++) {
            int m = row0 + ((i < 4) ? (ty * 4 + i) : (64 + ty * 4 + i - 4));
            float* crow = C + (size_t)m * N + col0;
            float4 lo = make_float4(acc[i][0], acc[i][1], acc[i][2], acc[i][3]);
            float4 hi = make_float4(acc[i][4], acc[i][5], acc[i][6], acc[i][7]);
            *(float4*)(crow + tx * 4)      = lo;
            *(float4*)(crow + 64 + tx * 4) = hi;
        }
    } else {
        // Context-select epilogue: out[m, o] = acc at column o*8 + ctx[m,o] (+bias)
        const int O = N >> 3;
#pragma unroll
        for (int i = 0; i < 8; i++) {
            int m = row0 + ((i < 4) ? (ty * 4 + i) : (64 + ty * 4 + i - 4));
            const unsigned char* cr = ctx + (size_t)m * O;
            float* orow = C + (size_t)m * O;
#pragma unroll
            for (int j = 0; j < 8; j++) {
                int n = col0 + ((j < 4) ? (tx * 4 + j) : (64 + tx * 4 + j - 4));
                int o = n >> 3;
                int c = n & 7;
                if ((int)cr[o] == c) {
                    float v = acc[i][j];
                    if (bias) v += bias[n];
                    orow[o] = v;
                }
            }
        }
    }
}

// ctx[b*O+o] = sum_s (S[b, o*3+s] > T[o*3+s]) << s, with fp64 rescue of any
// score within RESCUE_TAU of its threshold (sign decisions must be exact).
// S viewed as [B*O, 3] contiguous.  z: [B, K] (original input), H: [O*3, K].
__global__ void gln_combine(const float* __restrict__ S,
                            const float* __restrict__ T,
                            unsigned char* __restrict__ ctx,
                            const float* __restrict__ z,
                            const float* __restrict__ H,
                            int total, int O, int K)
{
    int i = blockIdx.x * blockDim.x + threadIdx.x;
    if (i >= total) return;
    int b = i / O;
    int o = i % O;
    const float* s = S + (size_t)i * 3;
    const float* t = T + (size_t)o * 3;
    int c = 0;
#pragma unroll
    for (int sb = 0; sb < 3; sb++) {
        float v  = s[sb];
        float th = t[sb];
        bool bit;
        if (fabsf(v - th) < RESCUE_TAU) {
            // Near the decision boundary: recompute the dot exactly (fp64).
            const float* zr = z + (size_t)b * K;
            const float* hr = H + (size_t)(o * 3 + sb) * K;
            double acc = 0.0;
            for (int k = 0; k < K; k++)
                acc += (double)zr[k] * (double)hr[k];
            bit = acc > (double)th;
        } else {
            bit = v > th;
        }
        c |= ((int)bit) << sb;
    }
    ctx[i] = (unsigned char)c;
}

extern "C" void kernel_launch(void* const* d_in, const int* in_sizes, int n_in,
                              void* d_out, int out_size)
{
    const float* x  = (const float*)d_in[0];
    const float* W0 = (const float*)d_in[1];
    const float* W1 = (const float*)d_in[2];
    const float* W2 = (const float*)d_in[3];
    const float* b1 = (const float*)d_in[4];
    const float* b2 = (const float*)d_in[5];
    const float* H0 = (const float*)d_in[6];
    const float* T0 = (const float*)d_in[7];
    const float* H1 = (const float*)d_in[8];
    const float* T1 = (const float*)d_in[9];
    const float* H2 = (const float*)d_in[10];
    const float* T2 = (const float*)d_in[11];
    float* out = (float*)d_out;

    void *pS, *ph0, *ph1, *pc0, *pc1, *pc2;
    cudaGetSymbolAddress(&pS,  g_S);
    cudaGetSymbolAddress(&ph0, g_h0);
    cudaGetSymbolAddress(&ph1, g_h1);
    cudaGetSymbolAddress(&pc0, g_ctx0);
    cudaGetSymbolAddress(&pc1, g_ctx1);
    cudaGetSymbolAddress(&pc2, g_ctx2);
    float* S  = (float*)pS;
    float* h0 = (float*)ph0;
    float* h1 = (float*)ph1;
    unsigned char* c0 = (unsigned char*)pc0;
    unsigned char* c1 = (unsigned char*)pc1;
    unsigned char* c2 = (unsigned char*)pc2;

    const int B     = 4096;
    const int D_IN  = 1024;
    const int D_LAT = 2048;
    const int D_OUT = 1024;

    dim3 blk(256);

    // ---- contexts (z = original x for all layers) ----
    gln_sgemm<0><<<dim3(B / BM, (D_LAT * 3) / BN), blk>>>(
        x, H0, S, nullptr, nullptr, B, D_LAT * 3, D_IN);
    gln_combine<<<(B * D_LAT + 255) / 256, 256>>>(S, T0, c0, x, H0,
                                                  B * D_LAT, D_LAT, D_IN);

    gln_sgemm<0><<<dim3(B / BM, (D_LAT * 3) / BN), blk>>>(
        x, H1, S, nullptr, nullptr, B, D_LAT * 3, D_IN);
    gln_combine<<<(B * D_LAT + 255) / 256, 256>>>(S, T1, c1, x, H1,
                                                  B * D_LAT, D_LAT, D_IN);

    gln_sgemm<0><<<dim3(B / BM, (D_OUT * 3) / BN), blk>>>(
        x, H2, S, nullptr, nullptr, B, D_OUT * 3, D_IN);
    gln_combine<<<(B * D_OUT + 255) / 256, 256>>>(S, T2, c2, x, H2,
                                                  B * D_OUT, D_OUT, D_IN);

    // ---- layers: dense GEMM + fused context select ----
    // Layer 0: h0 = select(x @ W0^T), no bias. N = D_LAT*8 = 16384, K = 1024
    gln_sgemm<1><<<dim3(B / BM, (D_LAT * 8) / BN), blk>>>(
        x, W0, h0, c0, nullptr, B, D_LAT * 8, D_IN);

    // Layer 1: h1 = select(h0 @ W1^T + b1). N = 16384, K = 2048
    gln_sgemm<1><<<dim3(B / BM, (D_LAT * 8) / BN), blk>>>(
        h0, W1, h1, c1, b1, B, D_LAT * 8, D_LAT);

    // Layer 2: out = select(h1 @ W2^T + b2). N = D_OUT*8 = 8192, K = 2048
    gln_sgemm<1><<<dim3(B / BM, (D_OUT * 8) / BN), blk>>>(
        h1, W2, out, c2, b2, B, D_OUT * 8, D_LAT);

    (void)in_sizes; (void)n_in; (void)out_size;
}

// round 4
// speedup vs baseline: 1.9008x; 1.9008x over previous
#include <cuda_runtime.h>
#include <cuda_bf16.h>
#include <cstdint>
#include <cstddef>
#include <math.h>

// ---------------------------------------------------------------------------
// GLN_56006373539841 via mma.sync (HMMA) bf16x3 split GEMM:
//   y = Ahi*Bhi + Alo*Bhi + Ahi*Blo, fp32 accumulate.
// compute_103-safe (no tcgen05). cp.async 4-stage pipeline + ldmatrix.
//   B=4096, D_IN=1024, D_LAT=2048, D_OUT=1024, SHATTER=3, NC=8
// ---------------------------------------------------------------------------

#define RESCUE_TAU 3e-3f
#define STAGES  4
#define KC      32
#define PITCH   80                  // 64B data + 16B pad: conflict-free ldsm
#define TILE_B  (128 * PITCH)       // 10240 B per tile (128 rows)
#define STAGE_B (4 * TILE_B)        // Ahi, Alo, Bhi, Blo
#define SMEM_SZ (STAGES * STAGE_B)  // 163840

// ============================ PTX helpers ==================================
__device__ __forceinline__ uint32_t smem_u32(const void* p) {
    uint32_t a;
    asm("{ .reg .u64 t; cvta.to.shared.u64 t, %1; cvt.u32.u64 %0, t; }"
        : "=r"(a) : "l"(p));
    return a;
}
__device__ __forceinline__ void cp16(uint32_t dst, const void* src) {
    asm volatile("cp.async.cg.shared.global [%0], [%1], 16;" :: "r"(dst), "l"(src));
}
#define CP_COMMIT() asm volatile("cp.async.commit_group;" ::: "memory")

__device__ __forceinline__ void ldsm4(uint32_t* r, uint32_t addr) {
    asm volatile("ldmatrix.sync.aligned.m8n8.x4.shared.b16 {%0,%1,%2,%3}, [%4];"
        : "=r"(r[0]), "=r"(r[1]), "=r"(r[2]), "=r"(r[3]) : "r"(addr));
}
__device__ __forceinline__ void hmma(float* d, const uint32_t* a, const uint32_t* b) {
    asm volatile("mma.sync.aligned.m16n8k16.row.col.f32.bf16.bf16.f32 "
        "{%0,%1,%2,%3},{%4,%5,%6,%7},{%8,%9},{%0,%1,%2,%3};"
        : "+f"(d[0]), "+f"(d[1]), "+f"(d[2]), "+f"(d[3])
        : "r"(a[0]), "r"(a[1]), "r"(a[2]), "r"(a[3]), "r"(b[0]), "r"(b[1]));
}

// ============================ scratch ======================================
__device__ __nv_bfloat16 g_xhi[4096u * 1024u];
__device__ __nv_bfloat16 g_xlo[4096u * 1024u];
__device__ __nv_bfloat16 g_hhi[4096u * 2048u];
__device__ __nv_bfloat16 g_hlo[4096u * 2048u];
__device__ __nv_bfloat16 g_bhi[16384u * 2048u];   // weight/H split (largest: W1)
__device__ __nv_bfloat16 g_blo[16384u * 2048u];
__device__ float         g_h  [4096u * 2048u];    // fp32 hidden staging
__device__ float         g_S  [4096u * 6144u];    // dense context scores
__device__ unsigned char g_ctx0[4096u * 2048u];
__device__ unsigned char g_ctx1[4096u * 2048u];
__device__ unsigned char g_ctx2[4096u * 1024u];

// ============================ split kernel =================================
__global__ void split_f32(const float* __restrict__ in,
                          __nv_bfloat16* __restrict__ hi,
                          __nv_bfloat16* __restrict__ lo, int n4)
{
    int i = blockIdx.x * blockDim.x + threadIdx.x;
    if (i >= n4) return;
    float4 v = ((const float4*)in)[i];
    __nv_bfloat16 h0 = __float2bfloat16(v.x), h1 = __float2bfloat16(v.y);
    __nv_bfloat16 h2 = __float2bfloat16(v.z), h3 = __float2bfloat16(v.w);
    __nv_bfloat16 l0 = __float2bfloat16(v.x - __bfloat162float(h0));
    __nv_bfloat16 l1 = __float2bfloat16(v.y - __bfloat162float(h1));
    __nv_bfloat16 l2 = __float2bfloat16(v.z - __bfloat162float(h2));
    __nv_bfloat16 l3 = __float2bfloat16(v.w - __bfloat162float(h3));
    ((__nv_bfloat162*)hi)[i * 2 + 0] = __nv_bfloat162(h0, h1);
    ((__nv_bfloat162*)hi)[i * 2 + 1] = __nv_bfloat162(h2, h3);
    ((__nv_bfloat162*)lo)[i * 2 + 0] = __nv_bfloat162(l0, l1);
    ((__nv_bfloat162*)lo)[i * 2 + 1] = __nv_bfloat162(l2, l3);
}

// ============================ main GEMM ====================================
// CTA 128M x 128N, 8 warps (4Mx2N), warp tile 32x64, m16n8k16 atoms.
// MODE 0: dense score store to outp[M,N].  MODE 1: 1-of-8 select (+bias).
template <int MODE>
__global__ __launch_bounds__(256, 1)
void mma_gemm(const __nv_bfloat16* __restrict__ Ahi, const __nv_bfloat16* __restrict__ Alo,
              const __nv_bfloat16* __restrict__ Bhi, const __nv_bfloat16* __restrict__ Blo,
              int K, int O, int N,
              float* __restrict__ outp,
              const unsigned char* __restrict__ ctx,
              const float* __restrict__ bias)
{
    extern __shared__ char smraw[];
    const uint32_t smb  = smem_u32(smraw);
    const int tid  = threadIdx.x;
    const int lane = tid & 31;
    const int wid  = tid >> 5;
    const int wm   = wid & 3;      // 0..3  (M)
    const int wn   = wid >> 2;     // 0..1  (N)
    const int row0 = blockIdx.x * 128;
    const int col0 = blockIdx.y * 128;

    const __nv_bfloat16* gsrc[4] = {
        Ahi + (size_t)row0 * K, Alo + (size_t)row0 * K,
        Bhi + (size_t)col0 * K, Blo + (size_t)col0 * K };

    float acc[2][8][4];
#pragma unroll
    for (int i = 0; i < 2; i++)
#pragma unroll
        for (int j = 0; j < 8; j++)
#pragma unroll
            for (int q = 0; q < 4; q++) acc[i][j][q] = 0.0f;

    const int nk = K / KC;   // >= 32

    auto issue = [&](int s) {
        uint32_t base = smb + (uint32_t)(s & (STAGES - 1)) * STAGE_B;
        int k0 = s * KC;
#pragma unroll
        for (int t = 0; t < 8; t++) {
            int id   = tid + t * 256;        // 0..2047
            int tile = id >> 9;              // 0..3
            int r    = (id >> 2) & 127;
            int c    = id & 3;
            cp16(base + tile * TILE_B + r * PITCH + c * 16,
                 gsrc[tile] + (size_t)r * K + k0 + c * 8);
        }
        CP_COMMIT();
    };

#pragma unroll
    for (int s = 0; s < STAGES - 1; s++) issue(s);

    const uint32_t lrow = (uint32_t)(lane & 15);
    const uint32_t lhal = (uint32_t)(lane >> 4) * 16;

    for (int it = 0; it < nk; it++) {
        asm volatile("cp.async.wait_group 2;" ::: "memory");
        __syncthreads();
        int pf = it + STAGES - 1;
        if (pf < nk) issue(pf); else CP_COMMIT();

        uint32_t stg = smb + (uint32_t)(it & (STAGES - 1)) * STAGE_B;
#pragma unroll
        for (int k16 = 0; k16 < 2; k16++) {
            uint32_t koff = lhal + (uint32_t)k16 * 32;
            uint32_t ah[2][4], al[2][4];
#pragma unroll
            for (int mi = 0; mi < 2; mi++) {
                uint32_t ro = (uint32_t)(wm * 32 + mi * 16) + lrow;
                ldsm4(ah[mi], stg + ro * PITCH + koff);
                ldsm4(al[mi], stg + TILE_B + ro * PITCH + koff);
            }
            uint32_t bh[8][2], bl[8][2];
#pragma unroll
            for (int jj = 0; jj < 4; jj++) {
                uint32_t ro = (uint32_t)(wn * 64 + jj * 16) + lrow;
                uint32_t r4[4];
                // matrices: m0=(n0-7,k0-7) m1=(n8-15,k0-7) m2=(n0-7,k8-15) m3=(n8-15,k8-15)
                ldsm4(r4, stg + 2 * TILE_B + ro * PITCH + koff);
                bh[jj * 2][0] = r4[0]; bh[jj * 2][1] = r4[2];       // b0 = k0-7, b1 = k8-15
                bh[jj * 2 + 1][0] = r4[1]; bh[jj * 2 + 1][1] = r4[3];
                ldsm4(r4, stg + 3 * TILE_B + ro * PITCH + koff);
                bl[jj * 2][0] = r4[0]; bl[jj * 2][1] = r4[2];
                bl[jj * 2 + 1][0] = r4[1]; bl[jj * 2 + 1][1] = r4[3];
            }
            // pass-major for ILP (16 independent accumulators per pass)
#pragma unroll
            for (int mi = 0; mi < 2; mi++)
#pragma unroll
                for (int nj = 0; nj < 8; nj++) hmma(acc[mi][nj], ah[mi], bh[nj]);
#pragma unroll
            for (int mi = 0; mi < 2; mi++)
#pragma unroll
                for (int nj = 0; nj < 8; nj++) hmma(acc[mi][nj], al[mi], bh[nj]);
#pragma unroll
            for (int mi = 0; mi < 2; mi++)
#pragma unroll
                for (int nj = 0; nj < 8; nj++) hmma(acc[mi][nj], ah[mi], bl[nj]);
        }
    }

    // ---------------- epilogue ----------------
    const int rr = lane >> 2;          // 0..7
    const int q2 = (lane & 3) * 2;     // col pair within n8

    if (MODE == 0) {
#pragma unroll
        for (int mi = 0; mi < 2; mi++) {
            int r_lo = row0 + wm * 32 + mi * 16 + rr;
            int r_hi = r_lo + 8;
#pragma unroll
            for (int nj = 0; nj < 8; nj++) {
                int n0 = col0 + wn * 64 + nj * 8 + q2;
                *(float2*)(outp + (size_t)r_lo * N + n0) =
                    make_float2(acc[mi][nj][0], acc[mi][nj][1]);
                *(float2*)(outp + (size_t)r_hi * N + n0) =
                    make_float2(acc[mi][nj][2], acc[mi][nj][3]);
            }
        }
    } else {
#pragma unroll
        for (int mi = 0; mi < 2; mi++) {
            int r_lo = row0 + wm * 32 + mi * 16 + rr;
            int r_hi = r_lo + 8;
#pragma unroll
            for (int nj = 0; nj < 8; nj++) {
                int o  = (col0 + wn * 64 + nj * 8) >> 3;
                int cb0 = ctx[(size_t)r_lo * O + o];
                int cb1 = ctx[(size_t)r_hi * O + o];
                if (cb0 == q2 || cb0 == q2 + 1) {
                    float v = (cb0 == q2) ? acc[mi][nj][0] : acc[mi][nj][1];
                    if (bias) v += bias[o * 8 + cb0];
                    outp[(size_t)r_lo * O + o] = v;
                }
                if (cb1 == q2 || cb1 == q2 + 1) {
                    float v = (cb1 == q2) ? acc[mi][nj][2] : acc[mi][nj][3];
                    if (bias) v += bias[o * 8 + cb1];
                    outp[(size_t)r_hi * O + o] = v;
                }
            }
        }
    }
}

// ============================ combine (+fp64 rescue) =======================
// S: [Brows, O*3] dense.  Thread handles 4 consecutive o's (12 floats, 3xfloat4).
__global__ void gln_combine(const float* __restrict__ S, const float* __restrict__ T,
                            unsigned char* __restrict__ ctx,
                            const float* __restrict__ z, const float* __restrict__ H,
                            int Brows, int O, int K)
{
    const int N  = O * 3;
    const int Oq = O >> 2;
    int i = blockIdx.x * blockDim.x + threadIdx.x;
    if (i >= Brows * Oq) return;
    int b  = i / Oq;
    int oq = i - b * Oq;
    int o0 = oq << 2;
    const float4* p = (const float4*)(S + (size_t)b * N + (size_t)o0 * 3);
    float4 v0 = p[0], v1 = p[1], v2 = p[2];
    float sv[12] = { v0.x, v0.y, v0.z, v0.w, v1.x, v1.y, v1.z, v1.w,
                     v2.x, v2.y, v2.z, v2.w };
    uint32_t word = 0;
#pragma unroll
    for (int j = 0; j < 4; j++) {
        int o = o0 + j;
        int c = 0;
#pragma unroll
        for (int s = 0; s < 3; s++) {
            float th = __ldg(T + o * 3 + s);
            float d  = sv[j * 3 + s] - th;
            bool bit;
            if (fabsf(d) < RESCUE_TAU) {
                const float* zr = z + (size_t)b * K;
                const float* hr = H + (size_t)(o * 3 + s) * K;
                double a2 = 0.0;
                for (int k = 0; k < K; k++)
                    a2 += (double)zr[k] * (double)hr[k];
                bit = a2 > (double)th;
            } else {
                bit = d > 0.0f;
            }
            c |= ((int)bit) << s;
        }
        word |= (uint32_t)c << (j * 8);
    }
    ((uint32_t*)ctx)[i] = word;
}

// ============================ host =========================================
extern "C" void kernel_launch(void* const* d_in, const int* in_sizes, int n_in,
                              void* d_out, int out_size)
{
    const float* x  = (const float*)d_in[0];
    const float* W0 = (const float*)d_in[1];
    const float* W1 = (const float*)d_in[2];
    const float* W2 = (const float*)d_in[3];
    const float* b1 = (const float*)d_in[4];
    const float* b2 = (const float*)d_in[5];
    const float* H0 = (const float*)d_in[6];
    const float* T0 = (const float*)d_in[7];
    const float* H1 = (const float*)d_in[8];
    const float* T1 = (const float*)d_in[9];
    const float* H2 = (const float*)d_in[10];
    const float* T2 = (const float*)d_in[11];
    float* out = (float*)d_out;

    void *pxh, *pxl, *phh, *phl, *pbh, *pbl, *ph, *pS, *pc0, *pc1, *pc2;
    cudaGetSymbolAddress(&pxh, g_xhi);  cudaGetSymbolAddress(&pxl, g_xlo);
    cudaGetSymbolAddress(&phh, g_hhi);  cudaGetSymbolAddress(&phl, g_hlo);
    cudaGetSymbolAddress(&pbh, g_bhi);  cudaGetSymbolAddress(&pbl, g_blo);
    cudaGetSymbolAddress(&ph,  g_h);    cudaGetSymbolAddress(&pS,  g_S);
    cudaGetSymbolAddress(&pc0, g_ctx0); cudaGetSymbolAddress(&pc1, g_ctx1);
    cudaGetSymbolAddress(&pc2, g_ctx2);
    __nv_bfloat16* xhi = (__nv_bfloat16*)pxh;  __nv_bfloat16* xlo = (__nv_bfloat16*)pxl;
    __nv_bfloat16* hhi = (__nv_bfloat16*)phh;  __nv_bfloat16* hlo = (__nv_bfloat16*)phl;
    __nv_bfloat16* bhi = (__nv_bfloat16*)pbh;  __nv_bfloat16* blo = (__nv_bfloat16*)pbl;
    float* h = (float*)ph;
    float* S = (float*)pS;
    unsigned char* c0 = (unsigned char*)pc0;
    unsigned char* c1 = (unsigned char*)pc1;
    unsigned char* c2 = (unsigned char*)pc2;

    const int B = 4096, DIN = 1024, DLAT = 2048, DOUT = 1024;

    cudaFuncSetAttribute(mma_gemm<0>, cudaFuncAttributeMaxDynamicSharedMemorySize, SMEM_SZ);
    cudaFuncSetAttribute(mma_gemm<1>, cudaFuncAttributeMaxDynamicSharedMemorySize, SMEM_SZ);

    auto splitN = [](const float* in, __nv_bfloat16* hi, __nv_bfloat16* lo, size_t n) {
        int n4 = (int)(n / 4);
        split_f32<<<(n4 + 255) / 256, 256>>>(in, hi, lo, n4);
    };

    // ---- split x once ----
    splitN(x, xhi, xlo, (size_t)B * DIN);

    // ---- context layers: scores -> combine(+rescue) ----
    splitN(H0, bhi, blo, (size_t)DLAT * 3 * DIN);
    mma_gemm<0><<<dim3(B / 128, (DLAT * 3) / 128), 256, SMEM_SZ>>>(
        xhi, xlo, bhi, blo, DIN, DLAT, DLAT * 3, S, nullptr, nullptr);
    gln_combine<<<(B * (DLAT / 4) + 255) / 256, 256>>>(S, T0, c0, x, H0, B, DLAT, DIN);

    splitN(H1, bhi, blo, (size_t)DLAT * 3 * DIN);
    mma_gemm<0><<<dim3(B / 128, (DLAT * 3) / 128), 256, SMEM_SZ>>>(
        xhi, xlo, bhi, blo, DIN, DLAT, DLAT * 3, S, nullptr, nullptr);
    gln_combine<<<(B * (DLAT / 4) + 255) / 256, 256>>>(S, T1, c1, x, H1, B, DLAT, DIN);

    splitN(H2, bhi, blo, (size_t)DOUT * 3 * DIN);
    mma_gemm<0><<<dim3(B / 128, (DOUT * 3) / 128), 256, SMEM_SZ>>>(
        xhi, xlo, bhi, blo, DIN, DOUT, DOUT * 3, S, nullptr, nullptr);
    gln_combine<<<(B * (DOUT / 4) + 255) / 256, 256>>>(S, T2, c2, x, H2, B, DOUT, DIN);

    // ---- layer 0: h = select(x @ W0^T), no bias ----
    splitN(W0, bhi, blo, (size_t)DLAT * 8 * DIN);
    mma_gemm<1><<<dim3(B / 128, (DLAT * 8) / 128), 256, SMEM_SZ>>>(
        xhi, xlo, bhi, blo, DIN, DLAT, DLAT * 8, h, c0, nullptr);

    // ---- layer 1: h = select(h @ W1^T + b1) ----
    splitN(h, hhi, hlo, (size_t)B * DLAT);
    splitN(W1, bhi, blo, (size_t)DLAT * 8 * DLAT);
    mma_gemm<1><<<dim3(B / 128, (DLAT * 8) / 128), 256, SMEM_SZ>>>(
        hhi, hlo, bhi, blo, DLAT, DLAT, DLAT * 8, h, c1, b1);

    // ---- layer 2: out = select(h @ W2^T + b2) ----
    splitN(h, hhi, hlo, (size_t)B * DLAT);
    splitN(W2, bhi, blo, (size_t)DOUT * 8 * DLAT);
    mma_gemm<1><<<dim3(B / 128, (DOUT * 8) / 128), 256, SMEM_SZ>>>(
        hhi, hlo, bhi, blo, DLAT, DOUT, DOUT * 8, out, c2, b2);

    (void)in_sizes; (void)n_in; (void)out_size;
}

// round 5
// speedup vs baseline: 2.3260x; 1.2237x over previous
#include <cuda_runtime.h>
#include <cuda_bf16.h>
#include <cstdint>
#include <cstddef>
#include <math.h>

// ---------------------------------------------------------------------------
// GLN_56006373539841: HMMA bf16x3 split GEMM (hi*hi + lo*hi + hi*lo, fp32 acc)
// R5: fused context-combine epilogue (NT=192), warp-cooperative fp64 rescue,
//     select epilogue emits bf16 hi/lo splits directly.
//   B=4096, D_IN=1024, D_LAT=2048, D_OUT=1024, SHATTER=3, NC=8
// ---------------------------------------------------------------------------

#define RESCUE_TAU 3e-3f
#define PITCH   80                    // 64B data + 16B pad (KC=32 bf16 rows)

// select-GEMM (NT=128): 4 stages
#define SSTAGES 4
#define S_TILE  (128 * PITCH)         // 10240
#define S_STAGE (4 * S_TILE)          // 40960
#define S_SMEM  (SSTAGES * S_STAGE)   // 163840

// ctx-GEMM (NT=192): 3 stages
#define CSTAGES 3
#define C_AB    (128 * PITCH)         // 10240
#define C_BB    (192 * PITCH)         // 15360
#define C_STAGE (2 * C_AB + 2 * C_BB) // 51200
#define C_SMEM  (CSTAGES * C_STAGE)   // 153600
#define SC_PITCH 194                  // score staging pitch (floats)

// ============================ PTX helpers ==================================
__device__ __forceinline__ uint32_t smem_u32(const void* p) {
    uint32_t a;
    asm("{ .reg .u64 t; cvta.to.shared.u64 t, %1; cvt.u32.u64 %0, t; }"
        : "=r"(a) : "l"(p));
    return a;
}
__device__ __forceinline__ void cp16(uint32_t dst, const void* src) {
    asm volatile("cp.async.cg.shared.global [%0], [%1], 16;" :: "r"(dst), "l"(src));
}
#define CP_COMMIT() asm volatile("cp.async.commit_group;" ::: "memory")

__device__ __forceinline__ void ldsm4(uint32_t* r, uint32_t addr) {
    asm volatile("ldmatrix.sync.aligned.m8n8.x4.shared.b16 {%0,%1,%2,%3}, [%4];"
        : "=r"(r[0]), "=r"(r[1]), "=r"(r[2]), "=r"(r[3]) : "r"(addr));
}
__device__ __forceinline__ void hmma(float* d, const uint32_t* a, const uint32_t* b) {
    asm volatile("mma.sync.aligned.m16n8k16.row.col.f32.bf16.bf16.f32 "
        "{%0,%1,%2,%3},{%4,%5,%6,%7},{%8,%9},{%0,%1,%2,%3};"
        : "+f"(d[0]), "+f"(d[1]), "+f"(d[2]), "+f"(d[3])
        : "r"(a[0]), "r"(a[1]), "r"(a[2]), "r"(a[3]), "r"(b[0]), "r"(b[1]));
}

// ============================ scratch ======================================
__device__ __nv_bfloat16 g_xhi [4096u * 1024u];
__device__ __nv_bfloat16 g_xlo [4096u * 1024u];
__device__ __nv_bfloat16 g_hAhi[4096u * 2048u];
__device__ __nv_bfloat16 g_hAlo[4096u * 2048u];
__device__ __nv_bfloat16 g_hBhi[4096u * 2048u];
__device__ __nv_bfloat16 g_hBlo[4096u * 2048u];
__device__ __nv_bfloat16 g_bhi [16384u * 2048u];   // weight/H split (largest: W1)
__device__ __nv_bfloat16 g_blo [16384u * 2048u];
__device__ unsigned char g_ctx0[4096u * 2048u];
__device__ unsigned char g_ctx1[4096u * 2048u];
__device__ unsigned char g_ctx2[4096u * 1024u];

// ============================ split kernel =================================
__global__ void split_f32(const float* __restrict__ in,
                          __nv_bfloat16* __restrict__ hi,
                          __nv_bfloat16* __restrict__ lo, int n4)
{
    int i = blockIdx.x * blockDim.x + threadIdx.x;
    if (i >= n4) return;
    float4 v = ((const float4*)in)[i];
    __nv_bfloat16 h0 = __float2bfloat16(v.x), h1 = __float2bfloat16(v.y);
    __nv_bfloat16 h2 = __float2bfloat16(v.z), h3 = __float2bfloat16(v.w);
    __nv_bfloat16 l0 = __float2bfloat16(v.x - __bfloat162float(h0));
    __nv_bfloat16 l1 = __float2bfloat16(v.y - __bfloat162float(h1));
    __nv_bfloat16 l2 = __float2bfloat16(v.z - __bfloat162float(h2));
    __nv_bfloat16 l3 = __float2bfloat16(v.w - __bfloat162float(h3));
    ((__nv_bfloat162*)hi)[i * 2 + 0] = __nv_bfloat162(h0, h1);
    ((__nv_bfloat162*)hi)[i * 2 + 1] = __nv_bfloat162(h2, h3);
    ((__nv_bfloat162*)lo)[i * 2 + 0] = __nv_bfloat162(l0, l1);
    ((__nv_bfloat162*)lo)[i * 2 + 1] = __nv_bfloat162(l2, l3);
}

// ============================ ctx GEMM (fused combine) =====================
// CTA 128M x 192N, 8 warps (4M x 2N), warp 32x96.  Scores -> smem -> ctx bytes
// (bit 0x80 flags |score-T| < RESCUE_TAU for the fp64 rescue pass).
__global__ __launch_bounds__(256, 1)
void gemm_ctx(const __nv_bfloat16* __restrict__ Ahi, const __nv_bfloat16* __restrict__ Alo,
              const __nv_bfloat16* __restrict__ Bhi, const __nv_bfloat16* __restrict__ Blo,
              int K, int O,
              unsigned char* __restrict__ ctxout, const float* __restrict__ T)
{
    extern __shared__ char smraw[];
    const uint32_t smb = smem_u32(smraw);
    const int tid  = threadIdx.x;
    const int lane = tid & 31;
    const int wid  = tid >> 5;
    const int wm   = wid & 3;
    const int wn   = wid >> 2;
    const int row0 = blockIdx.x * 128;
    const int col0 = blockIdx.y * 192;

    const __nv_bfloat16* gsrc[4] = {
        Ahi + (size_t)row0 * K, Alo + (size_t)row0 * K,
        Bhi + (size_t)col0 * K, Blo + (size_t)col0 * K };

    float acc[2][12][4];
#pragma unroll
    for (int i = 0; i < 2; i++)
#pragma unroll
        for (int j = 0; j < 12; j++)
#pragma unroll
            for (int q = 0; q < 4; q++) acc[i][j][q] = 0.0f;

    const int nk = K >> 5;

    auto issue = [&](unsigned s) {
        uint32_t base = smb + (s % 3u) * C_STAGE;
        int k0 = (int)s * 32;
        // A tiles: 1024 cp16
#pragma unroll
        for (int t = 0; t < 4; t++) {
            int id   = tid + t * 256;
            int tile = id >> 9;
            int r    = (id >> 2) & 127;
            int c    = id & 3;
            cp16(base + tile * C_AB + r * PITCH + c * 16,
                 gsrc[tile] + (size_t)r * K + k0 + c * 8);
        }
        // B tiles: 1536 cp16
#pragma unroll
        for (int t = 0; t < 6; t++) {
            int id = tid + t * 256;
            int r  = id >> 2;              // 0..383
            int tl = r >= 192;
            int rr = r - tl * 192;
            int c  = id & 3;
            cp16(base + 2 * C_AB + tl * C_BB + rr * PITCH + c * 16,
                 gsrc[2 + tl] + (size_t)rr * K + k0 + c * 8);
        }
        CP_COMMIT();
    };

    issue(0); issue(1);

    const uint32_t lrow = (uint32_t)(lane & 15);
    const uint32_t lhal = (uint32_t)(lane >> 4) * 16;

    for (int it = 0; it < nk; it++) {
        asm volatile("cp.async.wait_group 1;" ::: "memory");
        __syncthreads();
        int pf = it + 2;
        if (pf < nk) issue((unsigned)pf); else CP_COMMIT();

        uint32_t stg = smb + ((unsigned)it % 3u) * C_STAGE;
#pragma unroll
        for (int k16 = 0; k16 < 2; k16++) {
            uint32_t koff = lhal + (uint32_t)k16 * 32;
            uint32_t ah[2][4], al[2][4];
#pragma unroll
            for (int mi = 0; mi < 2; mi++) {
                uint32_t ro = (uint32_t)(wm * 32 + mi * 16) + lrow;
                ldsm4(ah[mi], stg + ro * PITCH + koff);
                ldsm4(al[mi], stg + C_AB + ro * PITCH + koff);
            }
            uint32_t bh[12][2], bl[12][2];
#pragma unroll
            for (int jj = 0; jj < 6; jj++) {
                uint32_t ro = (uint32_t)(wn * 96 + jj * 16) + lrow;
                uint32_t r4[4];
                ldsm4(r4, stg + 2 * C_AB + ro * PITCH + koff);
                bh[jj * 2][0] = r4[0]; bh[jj * 2][1] = r4[2];
                bh[jj * 2 + 1][0] = r4[1]; bh[jj * 2 + 1][1] = r4[3];
                ldsm4(r4, stg + 2 * C_AB + C_BB + ro * PITCH + koff);
                bl[jj * 2][0] = r4[0]; bl[jj * 2][1] = r4[2];
                bl[jj * 2 + 1][0] = r4[1]; bl[jj * 2 + 1][1] = r4[3];
            }
#pragma unroll
            for (int mi = 0; mi < 2; mi++)
#pragma unroll
                for (int nj = 0; nj < 12; nj++) hmma(acc[mi][nj], ah[mi], bh[nj]);
#pragma unroll
            for (int mi = 0; mi < 2; mi++)
#pragma unroll
                for (int nj = 0; nj < 12; nj++) hmma(acc[mi][nj], al[mi], bh[nj]);
#pragma unroll
            for (int mi = 0; mi < 2; mi++)
#pragma unroll
                for (int nj = 0; nj < 12; nj++) hmma(acc[mi][nj], ah[mi], bl[nj]);
        }
    }
    asm volatile("cp.async.wait_group 0;" ::: "memory");
    __syncthreads();

    // ---- stage scores into smem ----
    float* ssc = (float*)smraw;
    const int rr = lane >> 2;
    const int q2 = (lane & 3) * 2;
#pragma unroll
    for (int mi = 0; mi < 2; mi++) {
        int r_lo = wm * 32 + mi * 16 + rr;
        int r_hi = r_lo + 8;
#pragma unroll
        for (int nj = 0; nj < 12; nj++) {
            int c = wn * 96 + nj * 8 + q2;
            *(float2*)&ssc[r_lo * SC_PITCH + c] = make_float2(acc[mi][nj][0], acc[mi][nj][1]);
            *(float2*)&ssc[r_hi * SC_PITCH + c] = make_float2(acc[mi][nj][2], acc[mi][nj][3]);
        }
    }
    __syncthreads();

    // ---- combine: 128 rows x 64 groups -> 2048 uint32 words ----
    const int oc0 = col0 / 3;          // divisible by 64
#pragma unroll
    for (int w8 = 0; w8 < 8; w8++) {
        int word_id = tid + w8 * 256;  // 0..2047
        int r  = word_id >> 4;
        int wo = word_id & 15;
        const float* sp = ssc + r * SC_PITCH + wo * 12;
        uint32_t word = 0;
#pragma unroll
        for (int j = 0; j < 4; j++) {
            int o = oc0 + wo * 4 + j;
            int c = 0; bool fl = false;
#pragma unroll
            for (int s = 0; s < 3; s++) {
                float th = __ldg(T + o * 3 + s);
                float d  = sp[j * 3 + s] - th;
                c  |= ((int)(d > 0.0f)) << s;
                fl |= fabsf(d) < RESCUE_TAU;
            }
            word |= (uint32_t)((unsigned char)(c | (fl ? 0x80 : 0))) << (j * 8);
        }
        *(uint32_t*)(ctxout + (size_t)(row0 + r) * O + oc0 + wo * 4) = word;
    }
}

// ============================ warp-cooperative fp64 rescue =================
// Scan ctx words; each flagged entry recomputed by the whole warp. K = 1024.
__global__ void gln_rescue(unsigned char* __restrict__ ctx,
                           const float* __restrict__ z,
                           const float* __restrict__ H,
                           const float* __restrict__ T,
                           int total4, int O, int K)
{
    int i    = blockIdx.x * blockDim.x + threadIdx.x;
    int lane = threadIdx.x & 31;
    uint32_t w = (i < total4) ? ((const uint32_t*)ctx)[i] : 0u;
    unsigned m = __ballot_sync(0xFFFFFFFFu, (w & 0x80808080u) != 0u);
    while (m) {
        int src = __ffs(m) - 1; m &= m - 1;
        uint32_t sw = __shfl_sync(0xFFFFFFFFu, w, src);
        int si = __shfl_sync(0xFFFFFFFFu, i, src);
#pragma unroll
        for (int j = 0; j < 4; j++) {
            if (!((sw >> (j * 8)) & 0x80)) continue;
            int idx = si * 4 + j;
            int b = idx / O, o = idx - b * O;
            const float* zr = z + (size_t)b * K;
            int c = 0;
#pragma unroll
            for (int s = 0; s < 3; s++) {
                const float* hr = H + (size_t)(o * 3 + s) * K;
                double part = 0.0;
                for (int k = lane; k < K; k += 32)
                    part += (double)zr[k] * (double)hr[k];
#pragma unroll
                for (int off = 16; off; off >>= 1)
                    part += __shfl_down_sync(0xFFFFFFFFu, part, off);
                part = __shfl_sync(0xFFFFFFFFu, part, 0);
                c |= ((int)(part > (double)T[o * 3 + s])) << s;
            }
            if (lane == 0) ctx[idx] = (unsigned char)c;
        }
    }
}

// ============================ select GEMM ==================================
// CTA 128x128, 8 warps (4Mx2N), warp 32x64.
// MODE 1: hidden layer -> write bf16 hi/lo split.  MODE 2: final -> fp32.
template <int MODE>
__global__ __launch_bounds__(256, 1)
void gemm_sel(const __nv_bfloat16* __restrict__ Ahi, const __nv_bfloat16* __restrict__ Alo,
              const __nv_bfloat16* __restrict__ Bhi, const __nv_bfloat16* __restrict__ Blo,
              int K, int O,
              const unsigned char* __restrict__ ctx, const float* __restrict__ bias,
              float* __restrict__ outf,
              __nv_bfloat16* __restrict__ ohi, __nv_bfloat16* __restrict__ olo)
{
    extern __shared__ char smraw[];
    const uint32_t smb = smem_u32(smraw);
    const int tid  = threadIdx.x;
    const int lane = tid & 31;
    const int wid  = tid >> 5;
    const int wm   = wid & 3;
    const int wn   = wid >> 2;
    const int row0 = blockIdx.x * 128;
    const int col0 = blockIdx.y * 128;

    const __nv_bfloat16* gsrc[4] = {
        Ahi + (size_t)row0 * K, Alo + (size_t)row0 * K,
        Bhi + (size_t)col0 * K, Blo + (size_t)col0 * K };

    float acc[2][8][4];
#pragma unroll
    for (int i = 0; i < 2; i++)
#pragma unroll
        for (int j = 0; j < 8; j++)
#pragma unroll
            for (int q = 0; q < 4; q++) acc[i][j][q] = 0.0f;

    const int nk = K >> 5;

    auto issue = [&](int s) {
        uint32_t base = smb + (uint32_t)(s & (SSTAGES - 1)) * S_STAGE;
        int k0 = s * 32;
#pragma unroll
        for (int t = 0; t < 8; t++) {
            int id   = tid + t * 256;
            int tile = id >> 9;
            int r    = (id >> 2) & 127;
            int c    = id & 3;
            cp16(base + tile * S_TILE + r * PITCH + c * 16,
                 gsrc[tile] + (size_t)r * K + k0 + c * 8);
        }
        CP_COMMIT();
    };

#pragma unroll
    for (int s = 0; s < SSTAGES - 1; s++) issue(s);

    const uint32_t lrow = (uint32_t)(lane & 15);
    const uint32_t lhal = (uint32_t)(lane >> 4) * 16;

    for (int it = 0; it < nk; it++) {
        asm volatile("cp.async.wait_group 2;" ::: "memory");
        __syncthreads();
        int pf = it + SSTAGES - 1;
        if (pf < nk) issue(pf); else CP_COMMIT();

        uint32_t stg = smb + (uint32_t)(it & (SSTAGES - 1)) * S_STAGE;
#pragma unroll
        for (int k16 = 0; k16 < 2; k16++) {
            uint32_t koff = lhal + (uint32_t)k16 * 32;
            uint32_t ah[2][4], al[2][4];
#pragma unroll
            for (int mi = 0; mi < 2; mi++) {
                uint32_t ro = (uint32_t)(wm * 32 + mi * 16) + lrow;
                ldsm4(ah[mi], stg + ro * PITCH + koff);
                ldsm4(al[mi], stg + S_TILE + ro * PITCH + koff);
            }
            uint32_t bh[8][2], bl[8][2];
#pragma unroll
            for (int jj = 0; jj < 4; jj++) {
                uint32_t ro = (uint32_t)(wn * 64 + jj * 16) + lrow;
                uint32_t r4[4];
                ldsm4(r4, stg + 2 * S_TILE + ro * PITCH + koff);
                bh[jj * 2][0] = r4[0]; bh[jj * 2][1] = r4[2];
                bh[jj * 2 + 1][0] = r4[1]; bh[jj * 2 + 1][1] = r4[3];
                ldsm4(r4, stg + 3 * S_TILE + ro * PITCH + koff);
                bl[jj * 2][0] = r4[0]; bl[jj * 2][1] = r4[2];
                bl[jj * 2 + 1][0] = r4[1]; bl[jj * 2 + 1][1] = r4[3];
            }
#pragma unroll
            for (int mi = 0; mi < 2; mi++)
#pragma unroll
                for (int nj = 0; nj < 8; nj++) hmma(acc[mi][nj], ah[mi], bh[nj]);
#pragma unroll
            for (int mi = 0; mi < 2; mi++)
#pragma unroll
                for (int nj = 0; nj < 8; nj++) hmma(acc[mi][nj], al[mi], bh[nj]);
#pragma unroll
            for (int mi = 0; mi < 2; mi++)
#pragma unroll
                for (int nj = 0; nj < 8; nj++) hmma(acc[mi][nj], ah[mi], bl[nj]);
        }
    }

    // ---- 1-of-8 select epilogue ----
    const int rr = lane >> 2;
    const int q2 = (lane & 3) * 2;
#pragma unroll
    for (int mi = 0; mi < 2; mi++) {
        int r_lo = row0 + wm * 32 + mi * 16 + rr;
        int r_hi = r_lo + 8;
#pragma unroll
        for (int nj = 0; nj < 8; nj++) {
            int o   = (col0 + wn * 64 + nj * 8) >> 3;
            int cb0 = ctx[(size_t)r_lo * O + o];
            int cb1 = ctx[(size_t)r_hi * O + o];
            if (cb0 == q2 || cb0 == q2 + 1) {
                float v = (cb0 == q2) ? acc[mi][nj][0] : acc[mi][nj][1];
                if (bias) v += bias[o * 8 + cb0];
                size_t idx = (size_t)r_lo * O + o;
                if (MODE == 1) {
                    __nv_bfloat16 hb = __float2bfloat16(v);
                    ohi[idx] = hb;
                    olo[idx] = __float2bfloat16(v - __bfloat162float(hb));
                } else outf[idx] = v;
            }
            if (cb1 == q2 || cb1 == q2 + 1) {
                float v = (cb1 == q2) ? acc[mi][nj][2] : acc[mi][nj][3];
                if (bias) v += bias[o * 8 + cb1];
                size_t idx = (size_t)r_hi * O + o;
                if (MODE == 1) {
                    __nv_bfloat16 hb = __float2bfloat16(v);
                    ohi[idx] = hb;
                    olo[idx] = __float2bfloat16(v - __bfloat162float(hb));
                } else outf[idx] = v;
            }
        }
    }
}

// ============================ host =========================================
extern "C" void kernel_launch(void* const* d_in, const int* in_sizes, int n_in,
                              void* d_out, int out_size)
{
    const float* x  = (const float*)d_in[0];
    const float* W0 = (const float*)d_in[1];
    const float* W1 = (const float*)d_in[2];
    const float* W2 = (const float*)d_in[3];
    const float* b1 = (const float*)d_in[4];
    const float* b2 = (const float*)d_in[5];
    const float* H0 = (const float*)d_in[6];
    const float* T0 = (const float*)d_in[7];
    const float* H1 = (const float*)d_in[8];
    const float* T1 = (const float*)d_in[9];
    const float* H2 = (const float*)d_in[10];
    const float* T2 = (const float*)d_in[11];
    float* out = (float*)d_out;

    void *pxh, *pxl, *pah, *pal, *pbh2, *pbl2, *pwh, *pwl, *pc0, *pc1, *pc2;
    cudaGetSymbolAddress(&pxh,  g_xhi);  cudaGetSymbolAddress(&pxl,  g_xlo);
    cudaGetSymbolAddress(&pah,  g_hAhi); cudaGetSymbolAddress(&pal,  g_hAlo);
    cudaGetSymbolAddress(&pbh2, g_hBhi); cudaGetSymbolAddress(&pbl2, g_hBlo);
    cudaGetSymbolAddress(&pwh,  g_bhi);  cudaGetSymbolAddress(&pwl,  g_blo);
    cudaGetSymbolAddress(&pc0,  g_ctx0); cudaGetSymbolAddress(&pc1,  g_ctx1);
    cudaGetSymbolAddress(&pc2,  g_ctx2);
    __nv_bfloat16* xhi  = (__nv_bfloat16*)pxh;  __nv_bfloat16* xlo  = (__nv_bfloat16*)pxl;
    __nv_bfloat16* hAhi = (__nv_bfloat16*)pah;  __nv_bfloat16* hAlo = (__nv_bfloat16*)pal;
    __nv_bfloat16* hBhi = (__nv_bfloat16*)pbh2; __nv_bfloat16* hBlo = (__nv_bfloat16*)pbl2;
    __nv_bfloat16* whi  = (__nv_bfloat16*)pwh;  __nv_bfloat16* wlo  = (__nv_bfloat16*)pwl;
    unsigned char* c0 = (unsigned char*)pc0;
    unsigned char* c1 = (unsigned char*)pc1;
    unsigned char* c2 = (unsigned char*)pc2;

    const int B = 4096, DIN = 1024, DLAT = 2048, DOUT = 1024;

    cudaFuncSetAttribute(gemm_ctx,    cudaFuncAttributeMaxDynamicSharedMemorySize, C_SMEM);
    cudaFuncSetAttribute(gemm_sel<1>, cudaFuncAttributeMaxDynamicSharedMemorySize, S_SMEM);
    cudaFuncSetAttribute(gemm_sel<2>, cudaFuncAttributeMaxDynamicSharedMemorySize, S_SMEM);

    auto splitN = [](const float* in, __nv_bfloat16* hi, __nv_bfloat16* lo, size_t n) {
        int n4 = (int)(n / 4);
        split_f32<<<(n4 + 255) / 256, 256>>>(in, hi, lo, n4);
    };

    // ---- split x once ----
    splitN(x, xhi, xlo, (size_t)B * DIN);

    // ---- contexts: fused GEMM+combine, then warp-coop fp64 rescue ----
    splitN(H0, whi, wlo, (size_t)DLAT * 3 * DIN);
    gemm_ctx<<<dim3(B / 128, (DLAT * 3) / 192), 256, C_SMEM>>>(
        xhi, xlo, whi, wlo, DIN, DLAT, c0, T0);
    gln_rescue<<<(B * DLAT / 4 + 255) / 256, 256>>>(c0, x, H0, T0, B * DLAT / 4, DLAT, DIN);

    splitN(H1, whi, wlo, (size_t)DLAT * 3 * DIN);
    gemm_ctx<<<dim3(B / 128, (DLAT * 3) / 192), 256, C_SMEM>>>(
        xhi, xlo, whi, wlo, DIN, DLAT, c1, T1);
    gln_rescue<<<(B * DLAT / 4 + 255) / 256, 256>>>(c1, x, H1, T1, B * DLAT / 4, DLAT, DIN);

    splitN(H2, whi, wlo, (size_t)DOUT * 3 * DIN);
    gemm_ctx<<<dim3(B / 128, (DOUT * 3) / 192), 256, C_SMEM>>>(
        xhi, xlo, whi, wlo, DIN, DOUT, c2, T2);
    gln_rescue<<<(B * DOUT / 4 + 255) / 256, 256>>>(c2, x, H2, T2, B * DOUT / 4, DOUT, DIN);

    // ---- layer 0: hA = select(x @ W0^T), no bias ----
    splitN(W0, whi, wlo, (size_t)DLAT * 8 * DIN);
    gemm_sel<1><<<dim3(B / 128, (DLAT * 8) / 128), 256, S_SMEM>>>(
        xhi, xlo, whi, wlo, DIN, DLAT, c0, nullptr, nullptr, hAhi, hAlo);

    // ---- layer 1: hB = select(hA @ W1^T + b1) ----
    splitN(W1, whi, wlo, (size_t)DLAT * 8 * DLAT);
    gemm_sel<1><<<dim3(B / 128, (DLAT * 8) / 128), 256, S_SMEM>>>(
        hAhi, hAlo, whi, wlo, DLAT, DLAT, c1, b1, nullptr, hBhi, hBlo);

    // ---- layer 2: out = select(hB @ W2^T + b2) ----
    splitN(W2, whi, wlo, (size_t)DOUT * 8 * DLAT);
    gemm_sel<2><<<dim3(B / 128, (DOUT * 8) / 128), 256, S_SMEM>>>(
        hBhi, hBlo, whi, wlo, DLAT, DOUT, c2, b2, out, nullptr, nullptr);

    (void)in_sizes; (void)n_in; (void)out_size;
}

// round 6
// speedup vs baseline: 2.9715x; 1.2775x over previous
#include <cuda_runtime.h>
#include <cuda_fp16.h>
#include <cstdint>
#include <cstddef>
#include <math.h>

// ---------------------------------------------------------------------------
// GLN_56006373539841: HMMA fp16 split GEMM.
//   ctx GEMMs: single-pass fp16 (score err ~0.013) + tau=0.08 fp64 rescue
//   select GEMMs: 2-pass (Ahi*Bhi + Alo*Bhi), weights hi-only
//   B=4096, D_IN=1024, D_LAT=2048, D_OUT=1024, SHATTER=3, NC=8
// ---------------------------------------------------------------------------

#define RESCUE_TAU 0.08f
#define PITCH   80                    // 64B data + 16B pad (KC=32 fp16 rows)

// select GEMM (NT=128): 3 tiles (Ahi, Alo, Bhi), 4 stages
#define SSTAGES 4
#define S_TILE  (128 * PITCH)         // 10240
#define S_STAGE (3 * S_TILE)          // 30720
#define S_SMEM  (SSTAGES * S_STAGE)   // 122880

// ctx GEMM (NT=192): 2 tiles (Ahi, Bhi), 4 stages
#define CSTAGES 4
#define C_AB    (128 * PITCH)         // 10240
#define C_BB    (192 * PITCH)         // 15360
#define C_STAGE (C_AB + C_BB)         // 25600
#define C_SMEM  (CSTAGES * C_STAGE)   // 102400
#define SC_PITCH 194                  // score staging pitch (floats): 128*194*4=99328 <= C_SMEM

// ============================ PTX helpers ==================================
__device__ __forceinline__ uint32_t smem_u32(const void* p) {
    uint32_t a;
    asm("{ .reg .u64 t; cvta.to.shared.u64 t, %1; cvt.u32.u64 %0, t; }"
        : "=r"(a) : "l"(p));
    return a;
}
__device__ __forceinline__ void cp16(uint32_t dst, const void* src) {
    asm volatile("cp.async.cg.shared.global [%0], [%1], 16;" :: "r"(dst), "l"(src));
}
#define CP_COMMIT() asm volatile("cp.async.commit_group;" ::: "memory")

__device__ __forceinline__ void ldsm4(uint32_t* r, uint32_t addr) {
    asm volatile("ldmatrix.sync.aligned.m8n8.x4.shared.b16 {%0,%1,%2,%3}, [%4];"
        : "=r"(r[0]), "=r"(r[1]), "=r"(r[2]), "=r"(r[3]) : "r"(addr));
}
__device__ __forceinline__ void hmma(float* d, const uint32_t* a, const uint32_t* b) {
    asm volatile("mma.sync.aligned.m16n8k16.row.col.f32.f16.f16.f32 "
        "{%0,%1,%2,%3},{%4,%5,%6,%7},{%8,%9},{%0,%1,%2,%3};"
        : "+f"(d[0]), "+f"(d[1]), "+f"(d[2]), "+f"(d[3])
        : "r"(a[0]), "r"(a[1]), "r"(a[2]), "r"(a[3]), "r"(b[0]), "r"(b[1]));
}

// ============================ scratch ======================================
__device__ __half g_xhi [4096u * 1024u];
__device__ __half g_xlo [4096u * 1024u];
__device__ __half g_hAhi[4096u * 2048u];
__device__ __half g_hAlo[4096u * 2048u];
__device__ __half g_hBhi[4096u * 2048u];
__device__ __half g_hBlo[4096u * 2048u];
__device__ __half g_whi [16384u * 2048u];   // weight/H hi (largest: W1)
__device__ unsigned char g_ctx0[4096u * 2048u];
__device__ unsigned char g_ctx1[4096u * 2048u];
__device__ unsigned char g_ctx2[4096u * 1024u];

// ============================ convert kernels ==============================
__global__ void split_hilo(const float* __restrict__ in,
                           __half* __restrict__ hi, __half* __restrict__ lo, int n4)
{
    int i = blockIdx.x * blockDim.x + threadIdx.x;
    if (i >= n4) return;
    float4 v = ((const float4*)in)[i];
    __half h0 = __float2half_rn(v.x), h1 = __float2half_rn(v.y);
    __half h2 = __float2half_rn(v.z), h3 = __float2half_rn(v.w);
    __half l0 = __float2half_rn(v.x - __half2float(h0));
    __half l1 = __float2half_rn(v.y - __half2float(h1));
    __half l2 = __float2half_rn(v.z - __half2float(h2));
    __half l3 = __float2half_rn(v.w - __half2float(h3));
    ((__half2*)hi)[i * 2 + 0] = __halves2half2(h0, h1);
    ((__half2*)hi)[i * 2 + 1] = __halves2half2(h2, h3);
    ((__half2*)lo)[i * 2 + 0] = __halves2half2(l0, l1);
    ((__half2*)lo)[i * 2 + 1] = __halves2half2(l2, l3);
}

__global__ void conv_hi(const float* __restrict__ in, __half* __restrict__ hi, int n4)
{
    int i = blockIdx.x * blockDim.x + threadIdx.x;
    if (i >= n4) return;
    float4 v = ((const float4*)in)[i];
    ((__half2*)hi)[i * 2 + 0] = __halves2half2(__float2half_rn(v.x), __float2half_rn(v.y));
    ((__half2*)hi)[i * 2 + 1] = __halves2half2(__float2half_rn(v.z), __float2half_rn(v.w));
}

// ============================ ctx GEMM (fused combine) =====================
// CTA 128M x 192N, 8 warps (4M x 2N), warp 32x96.  Single-pass fp16.
// Output byte: bits 0-2 ctx index, bits 3-5 per-score rescue flags.
__global__ __launch_bounds__(256, 1)
void gemm_ctx(const __half* __restrict__ Ahi, const __half* __restrict__ Bhi,
              int K, int O,
              unsigned char* __restrict__ ctxout, const float* __restrict__ T)
{
    extern __shared__ char smraw[];
    const uint32_t smb = smem_u32(smraw);
    const int tid  = threadIdx.x;
    const int lane = tid & 31;
    const int wid  = tid >> 5;
    const int wm   = wid & 3;
    const int wn   = wid >> 2;
    const int row0 = blockIdx.x * 128;
    const int col0 = blockIdx.y * 192;

    const __half* gA = Ahi + (size_t)row0 * K;
    const __half* gB = Bhi + (size_t)col0 * K;

    float acc[2][12][4];
#pragma unroll
    for (int i = 0; i < 2; i++)
#pragma unroll
        for (int j = 0; j < 12; j++)
#pragma unroll
            for (int q = 0; q < 4; q++) acc[i][j][q] = 0.0f;

    const int nk = K >> 5;

    auto issue = [&](int s) {
        uint32_t base = smb + (uint32_t)(s & (CSTAGES - 1)) * C_STAGE;
        int k0 = s * 32;
#pragma unroll
        for (int t = 0; t < 2; t++) {           // A: 512 cp16
            int id = tid + t * 256;
            int r  = id >> 2, c = id & 3;
            cp16(base + r * PITCH + c * 16, gA + (size_t)r * K + k0 + c * 8);
        }
#pragma unroll
        for (int t = 0; t < 3; t++) {           // B: 768 cp16
            int id = tid + t * 256;
            int r  = id >> 2, c = id & 3;
            cp16(base + C_AB + r * PITCH + c * 16, gB + (size_t)r * K + k0 + c * 8);
        }
        CP_COMMIT();
    };

#pragma unroll
    for (int s = 0; s < CSTAGES - 1; s++) issue(s);

    const uint32_t lrow = (uint32_t)(lane & 15);
    const uint32_t lhal = (uint32_t)(lane >> 4) * 16;

    for (int it = 0; it < nk; it++) {
        asm volatile("cp.async.wait_group 2;" ::: "memory");
        __syncthreads();
        int pf = it + CSTAGES - 1;
        if (pf < nk) issue(pf); else CP_COMMIT();

        uint32_t stg = smb + (uint32_t)(it & (CSTAGES - 1)) * C_STAGE;
#pragma unroll
        for (int k16 = 0; k16 < 2; k16++) {
            uint32_t koff = lhal + (uint32_t)k16 * 32;
            uint32_t ah[2][4];
#pragma unroll
            for (int mi = 0; mi < 2; mi++) {
                uint32_t ro = (uint32_t)(wm * 32 + mi * 16) + lrow;
                ldsm4(ah[mi], stg + ro * PITCH + koff);
            }
            uint32_t bh[12][2];
#pragma unroll
            for (int jj = 0; jj < 6; jj++) {
                uint32_t ro = (uint32_t)(wn * 96 + jj * 16) + lrow;
                uint32_t r4[4];
                ldsm4(r4, stg + C_AB + ro * PITCH + koff);
                bh[jj * 2][0] = r4[0]; bh[jj * 2][1] = r4[2];
                bh[jj * 2 + 1][0] = r4[1]; bh[jj * 2 + 1][1] = r4[3];
            }
#pragma unroll
            for (int mi = 0; mi < 2; mi++)
#pragma unroll
                for (int nj = 0; nj < 12; nj++) hmma(acc[mi][nj], ah[mi], bh[nj]);
        }
    }
    asm volatile("cp.async.wait_group 0;" ::: "memory");
    __syncthreads();

    // ---- stage scores into smem ----
    float* ssc = (float*)smraw;
    const int rr = lane >> 2;
    const int q2 = (lane & 3) * 2;
#pragma unroll
    for (int mi = 0; mi < 2; mi++) {
        int r_lo = wm * 32 + mi * 16 + rr;
        int r_hi = r_lo + 8;
#pragma unroll
        for (int nj = 0; nj < 12; nj++) {
            int c = wn * 96 + nj * 8 + q2;
            *(float2*)&ssc[r_lo * SC_PITCH + c] = make_float2(acc[mi][nj][0], acc[mi][nj][1]);
            *(float2*)&ssc[r_hi * SC_PITCH + c] = make_float2(acc[mi][nj][2], acc[mi][nj][3]);
        }
    }
    __syncthreads();

    // ---- combine: 128 rows x 64 o-groups -> 2048 uint32 words ----
    const int oc0 = col0 / 3;
#pragma unroll
    for (int w8 = 0; w8 < 8; w8++) {
        int word_id = tid + w8 * 256;
        int r  = word_id >> 4;
        int wo = word_id & 15;
        const float* sp = ssc + r * SC_PITCH + wo * 12;
        uint32_t word = 0;
#pragma unroll
        for (int j = 0; j < 4; j++) {
            int o = oc0 + wo * 4 + j;
            int c = 0;
#pragma unroll
            for (int s = 0; s < 3; s++) {
                float th = __ldg(T + o * 3 + s);
                float d  = sp[j * 3 + s] - th;
                c |= ((int)(d > 0.0f)) << s;
                c |= ((int)(fabsf(d) < RESCUE_TAU)) << (3 + s);
            }
            word |= (uint32_t)((unsigned char)c) << (j * 8);
        }
        *(uint32_t*)(ctxout + (size_t)(row0 + r) * O + oc0 + wo * 4) = word;
    }
}

// ============================ warp-cooperative fp64 rescue =================
// Per-score flags (bits 3-5). Recompute only flagged scores; clear flags.
__global__ void gln_rescue(unsigned char* __restrict__ ctx,
                           const float* __restrict__ z,
                           const float* __restrict__ H,
                           const float* __restrict__ T,
                           int total4, int O, int K)
{
    int i    = blockIdx.x * blockDim.x + threadIdx.x;
    int lane = threadIdx.x & 31;
    uint32_t w = (i < total4) ? ((const uint32_t*)ctx)[i] : 0u;
    unsigned m = __ballot_sync(0xFFFFFFFFu, (w & 0x38383838u) != 0u);
    bool drop_flags = (i < total4) && (w & 0x38383838u);
    while (m) {
        int src = __ffs(m) - 1; m &= m - 1;
        uint32_t sw = __shfl_sync(0xFFFFFFFFu, w, src);
        int si = __shfl_sync(0xFFFFFFFFu, i, src);
#pragma unroll
        for (int j = 0; j < 4; j++) {
            uint32_t byte = (sw >> (j * 8)) & 0xFF;
            if (!(byte & 0x38)) continue;
            int idx = si * 4 + j;
            int b = idx / O, o = idx - b * O;
            const float* zr = z + (size_t)b * K;
            int c = (int)(byte & 7);
#pragma unroll
            for (int s = 0; s < 3; s++) {
                if (!(byte & (8u << s))) continue;
                const float* hr = H + (size_t)(o * 3 + s) * K;
                double part = 0.0;
                for (int k = lane; k < K; k += 32)
                    part += (double)zr[k] * (double)hr[k];
#pragma unroll
                for (int off = 16; off; off >>= 1)
                    part += __shfl_down_sync(0xFFFFFFFFu, part, off);
                part = __shfl_sync(0xFFFFFFFFu, part, 0);
                c = (c & ~(1 << s)) | (((int)(part > (double)T[o * 3 + s])) << s);
            }
            if (lane == 0) ctx[idx] = (unsigned char)c;
        }
    }
    // entries whose word had flags were rewritten byte-wise above; nothing else to do
    (void)drop_flags;
}

// ============================ select GEMM ==================================
// CTA 128x128, 8 warps (4Mx2N), warp 32x64. 2-pass: Ahi*Bhi + Alo*Bhi.
// MODE 1: hidden -> fp16 hi/lo.  MODE 2: final -> fp32.
template <int MODE>
__global__ __launch_bounds__(256, 1)
void gemm_sel(const __half* __restrict__ Ahi, const __half* __restrict__ Alo,
              const __half* __restrict__ Bhi,
              int K, int O,
              const unsigned char* __restrict__ ctx, const float* __restrict__ bias,
              float* __restrict__ outf,
              __half* __restrict__ ohi, __half* __restrict__ olo)
{
    extern __shared__ char smraw[];
    const uint32_t smb = smem_u32(smraw);
    const int tid  = threadIdx.x;
    const int lane = tid & 31;
    const int wid  = tid >> 5;
    const int wm   = wid & 3;
    const int wn   = wid >> 2;
    const int row0 = blockIdx.x * 128;
    const int col0 = blockIdx.y * 128;

    const __half* gsrc[3] = {
        Ahi + (size_t)row0 * K, Alo + (size_t)row0 * K, Bhi + (size_t)col0 * K };

    float acc[2][8][4];
#pragma unroll
    for (int i = 0; i < 2; i++)
#pragma unroll
        for (int j = 0; j < 8; j++)
#pragma unroll
            for (int q = 0; q < 4; q++) acc[i][j][q] = 0.0f;

    const int nk = K >> 5;

    auto issue = [&](int s) {
        uint32_t base = smb + (uint32_t)(s & (SSTAGES - 1)) * S_STAGE;
        int k0 = s * 32;
#pragma unroll
        for (int t = 0; t < 6; t++) {           // 1536 cp16
            int id   = tid + t * 256;
            int tile = id >> 9;                 // 0..2
            int r    = (id >> 2) & 127;
            int c    = id & 3;
            cp16(base + tile * S_TILE + r * PITCH + c * 16,
                 gsrc[tile] + (size_t)r * K + k0 + c * 8);
        }
        CP_COMMIT();
    };

#pragma unroll
    for (int s = 0; s < SSTAGES - 1; s++) issue(s);

    const uint32_t lrow = (uint32_t)(lane & 15);
    const uint32_t lhal = (uint32_t)(lane >> 4) * 16;

    for (int it = 0; it < nk; it++) {
        asm volatile("cp.async.wait_group 2;" ::: "memory");
        __syncthreads();
        int pf = it + SSTAGES - 1;
        if (pf < nk) issue(pf); else CP_COMMIT();

        uint32_t stg = smb + (uint32_t)(it & (SSTAGES - 1)) * S_STAGE;
#pragma unroll
        for (int k16 = 0; k16 < 2; k16++) {
            uint32_t koff = lhal + (uint32_t)k16 * 32;
            uint32_t ah[2][4], al[2][4];
#pragma unroll
            for (int mi = 0; mi < 2; mi++) {
                uint32_t ro = (uint32_t)(wm * 32 + mi * 16) + lrow;
                ldsm4(ah[mi], stg + ro * PITCH + koff);
                ldsm4(al[mi], stg + S_TILE + ro * PITCH + koff);
            }
            uint32_t bh[8][2];
#pragma unroll
            for (int jj = 0; jj < 4; jj++) {
                uint32_t ro = (uint32_t)(wn * 64 + jj * 16) + lrow;
                uint32_t r4[4];
                ldsm4(r4, stg + 2 * S_TILE + ro * PITCH + koff);
                bh[jj * 2][0] = r4[0]; bh[jj * 2][1] = r4[2];
                bh[jj * 2 + 1][0] = r4[1]; bh[jj * 2 + 1][1] = r4[3];
            }
#pragma unroll
            for (int mi = 0; mi < 2; mi++)
#pragma unroll
                for (int nj = 0; nj < 8; nj++) hmma(acc[mi][nj], ah[mi], bh[nj]);
#pragma unroll
            for (int mi = 0; mi < 2; mi++)
#pragma unroll
                for (int nj = 0; nj < 8; nj++) hmma(acc[mi][nj], al[mi], bh[nj]);
        }
    }

    // ---- 1-of-8 select epilogue ----
    const int rr = lane >> 2;
    const int q2 = (lane & 3) * 2;
#pragma unroll
    for (int mi = 0; mi < 2; mi++) {
        int r_lo = row0 + wm * 32 + mi * 16 + rr;
        int r_hi = r_lo + 8;
#pragma unroll
        for (int nj = 0; nj < 8; nj++) {
            int o   = (col0 + wn * 64 + nj * 8) >> 3;
            int cb0 = ctx[(size_t)r_lo * O + o] & 7;
            int cb1 = ctx[(size_t)r_hi * O + o] & 7;
            if (cb0 == q2 || cb0 == q2 + 1) {
                float v = (cb0 == q2) ? acc[mi][nj][0] : acc[mi][nj][1];
                if (bias) v += bias[o * 8 + cb0];
                size_t idx = (size_t)r_lo * O + o;
                if (MODE == 1) {
                    __half hb = __float2half_rn(v);
                    ohi[idx] = hb;
                    olo[idx] = __float2half_rn(v - __half2float(hb));
                } else outf[idx] = v;
            }
            if (cb1 == q2 || cb1 == q2 + 1) {
                float v = (cb1 == q2) ? acc[mi][nj][2] : acc[mi][nj][3];
                if (bias) v += bias[o * 8 + cb1];
                size_t idx = (size_t)r_hi * O + o;
                if (MODE == 1) {
                    __half hb = __float2half_rn(v);
                    ohi[idx] = hb;
                    olo[idx] = __float2half_rn(v - __half2float(hb));
                } else outf[idx] = v;
            }
        }
    }
}

// ============================ host =========================================
extern "C" void kernel_launch(void* const* d_in, const int* in_sizes, int n_in,
                              void* d_out, int out_size)
{
    const float* x  = (const float*)d_in[0];
    const float* W0 = (const float*)d_in[1];
    const float* W1 = (const float*)d_in[2];
    const float* W2 = (const float*)d_in[3];
    const float* b1 = (const float*)d_in[4];
    const float* b2 = (const float*)d_in[5];
    const float* H0 = (const float*)d_in[6];
    const float* T0 = (const float*)d_in[7];
    const float* H1 = (const float*)d_in[8];
    const float* T1 = (const float*)d_in[9];
    const float* H2 = (const float*)d_in[10];
    const float* T2 = (const float*)d_in[11];
    float* out = (float*)d_out;

    void *pxh, *pxl, *pah, *pal, *pbh, *pbl, *pwh, *pc0, *pc1, *pc2;
    cudaGetSymbolAddress(&pxh, g_xhi);  cudaGetSymbolAddress(&pxl, g_xlo);
    cudaGetSymbolAddress(&pah, g_hAhi); cudaGetSymbolAddress(&pal, g_hAlo);
    cudaGetSymbolAddress(&pbh, g_hBhi); cudaGetSymbolAddress(&pbl, g_hBlo);
    cudaGetSymbolAddress(&pwh, g_whi);
    cudaGetSymbolAddress(&pc0, g_ctx0); cudaGetSymbolAddress(&pc1, g_ctx1);
    cudaGetSymbolAddress(&pc2, g_ctx2);
    __half* xhi  = (__half*)pxh;  __half* xlo  = (__half*)pxl;
    __half* hAhi = (__half*)pah;  __half* hAlo = (__half*)pal;
    __half* hBhi = (__half*)pbh;  __half* hBlo = (__half*)pbl;
    __half* whi  = (__half*)pwh;
    unsigned char* c0 = (unsigned char*)pc0;
    unsigned char* c1 = (unsigned char*)pc1;
    unsigned char* c2 = (unsigned char*)pc2;

    const int B = 4096, DIN = 1024, DLAT = 2048, DOUT = 1024;

    cudaFuncSetAttribute(gemm_ctx,    cudaFuncAttributeMaxDynamicSharedMemorySize, C_SMEM);
    cudaFuncSetAttribute(gemm_sel<1>, cudaFuncAttributeMaxDynamicSharedMemorySize, S_SMEM);
    cudaFuncSetAttribute(gemm_sel<2>, cudaFuncAttributeMaxDynamicSharedMemorySize, S_SMEM);

    auto convW = [&](const float* in, size_t n) {
        int n4 = (int)(n / 4);
        conv_hi<<<(n4 + 255) / 256, 256>>>(in, whi, n4);
    };

    // ---- split x (hi+lo) ----
    {
        int n4 = B * DIN / 4;
        split_hilo<<<(n4 + 255) / 256, 256>>>(x, xhi, xlo, n4);
    }

    // ---- contexts: single-pass fp16 GEMM+combine, then fp64 rescue ----
    convW(H0, (size_t)DLAT * 3 * DIN);
    gemm_ctx<<<dim3(B / 128, (DLAT * 3) / 192), 256, C_SMEM>>>(xhi, whi, DIN, DLAT, c0, T0);
    gln_rescue<<<(B * DLAT / 4 + 255) / 256, 256>>>(c0, x, H0, T0, B * DLAT / 4, DLAT, DIN);

    convW(H1, (size_t)DLAT * 3 * DIN);
    gemm_ctx<<<dim3(B / 128, (DLAT * 3) / 192), 256, C_SMEM>>>(xhi, whi, DIN, DLAT, c1, T1);
    gln_rescue<<<(B * DLAT / 4 + 255) / 256, 256>>>(c1, x, H1, T1, B * DLAT / 4, DLAT, DIN);

    convW(H2, (size_t)DOUT * 3 * DIN);
    gemm_ctx<<<dim3(B / 128, (DOUT * 3) / 192), 256, C_SMEM>>>(xhi, whi, DIN, DOUT, c2, T2);
    gln_rescue<<<(B * DOUT / 4 + 255) / 256, 256>>>(c2, x, H2, T2, B * DOUT / 4, DOUT, DIN);

    // ---- layer 0: hA = select(x @ W0^T), no bias ----
    convW(W0, (size_t)DLAT * 8 * DIN);
    gemm_sel<1><<<dim3(B / 128, (DLAT * 8) / 128), 256, S_SMEM>>>(
        xhi, xlo, whi, DIN, DLAT, c0, nullptr, nullptr, hAhi, hAlo);

    // ---- layer 1: hB = select(hA @ W1^T + b1) ----
    convW(W1, (size_t)DLAT * 8 * DLAT);
    gemm_sel<1><<<dim3(B / 128, (DLAT * 8) / 128), 256, S_SMEM>>>(
        hAhi, hAlo, whi, DLAT, DLAT, c1, b1, nullptr, hBhi, hBlo);

    // ---- layer 2: out = select(hB @ W2^T + b2) ----
    convW(W2, (size_t)DOUT * 8 * DLAT);
    gemm_sel<2><<<dim3(B / 128, (DOUT * 8) / 128), 256, S_SMEM>>>(
        hBhi, hBlo, whi, DLAT, DOUT, c2, b2, out, nullptr, nullptr);

    (void)in_sizes; (void)n_in; (void)out_size;
}

// round 7
// speedup vs baseline: 4.7729x; 1.6063x over previous
#include <cuda_runtime.h>
#include <cuda_fp16.h>
#include <cstdint>
#include <cstddef>
#include <math.h>

// ---------------------------------------------------------------------------
// GLN_56006373539841: HMMA fp16 GEMM, single-pass everywhere.
//   ctx GEMMs: fp16 (score err ~0.011) + tau=0.08 fp64 rescue of near-
//              threshold sign decisions (fused flagging in epilogue)
//   select GEMMs: single-pass fp16 (A-hi x B-hi), hidden h stored fp16
//   B=4096, D_IN=1024, D_LAT=2048, D_OUT=1024, SHATTER=3, NC=8
// ---------------------------------------------------------------------------

#define RESCUE_TAU 0.08f
#define PITCH   80                    // 64B data + 16B pad (KC=32 fp16 rows)

// select GEMM (NT=128): 2 tiles (A, B), 4 stages
#define SSTAGES 4
#define S_TILE  (128 * PITCH)         // 10240
#define S_STAGE (2 * S_TILE)          // 20480
#define S_SMEM  (SSTAGES * S_STAGE)   // 81920

// ctx GEMM (NT=192): 2 tiles (A, B), 4 stages
#define CSTAGES 4
#define C_AB    (128 * PITCH)         // 10240
#define C_BB    (192 * PITCH)         // 15360
#define C_STAGE (C_AB + C_BB)         // 25600
#define C_SMEM  (CSTAGES * C_STAGE)   // 102400
#define SC_PITCH 194                  // score staging pitch (floats)

// ============================ PTX helpers ==================================
__device__ __forceinline__ uint32_t smem_u32(const void* p) {
    uint32_t a;
    asm("{ .reg .u64 t; cvta.to.shared.u64 t, %1; cvt.u32.u64 %0, t; }"
        : "=r"(a) : "l"(p));
    return a;
}
__device__ __forceinline__ void cp16(uint32_t dst, const void* src) {
    asm volatile("cp.async.cg.shared.global [%0], [%1], 16;" :: "r"(dst), "l"(src));
}
#define CP_COMMIT() asm volatile("cp.async.commit_group;" ::: "memory")

__device__ __forceinline__ void ldsm4(uint32_t* r, uint32_t addr) {
    asm volatile("ldmatrix.sync.aligned.m8n8.x4.shared.b16 {%0,%1,%2,%3}, [%4];"
        : "=r"(r[0]), "=r"(r[1]), "=r"(r[2]), "=r"(r[3]) : "r"(addr));
}
__device__ __forceinline__ void hmma(float* d, const uint32_t* a, const uint32_t* b) {
    asm volatile("mma.sync.aligned.m16n8k16.row.col.f32.f16.f16.f32 "
        "{%0,%1,%2,%3},{%4,%5,%6,%7},{%8,%9},{%0,%1,%2,%3};"
        : "+f"(d[0]), "+f"(d[1]), "+f"(d[2]), "+f"(d[3])
        : "r"(a[0]), "r"(a[1]), "r"(a[2]), "r"(a[3]), "r"(b[0]), "r"(b[1]));
}

// ============================ scratch ======================================
__device__ __half g_xh [4096u * 1024u];
__device__ __half g_hA [4096u * 2048u];
__device__ __half g_hB [4096u * 2048u];
__device__ __half g_whA[6144u * 1024u];     // H conversions (contexts)
__device__ __half g_whB[16384u * 2048u];    // W conversions (largest: W1)
__device__ unsigned char g_ctx0[4096u * 2048u];
__device__ unsigned char g_ctx1[4096u * 2048u];
__device__ unsigned char g_ctx2[4096u * 1024u];

// ============================ convert kernel ===============================
__global__ void conv_hi(const float* __restrict__ in, __half* __restrict__ hi, int n4)
{
    int i = blockIdx.x * blockDim.x + threadIdx.x;
    if (i >= n4) return;
    float4 v = ((const float4*)in)[i];
    ((__half2*)hi)[i * 2 + 0] = __halves2half2(__float2half_rn(v.x), __float2half_rn(v.y));
    ((__half2*)hi)[i * 2 + 1] = __halves2half2(__float2half_rn(v.z), __float2half_rn(v.w));
}

// ============================ ctx GEMM (fused combine) =====================
// CTA 128M x 192N, 8 warps (4M x 2N), warp 32x96.  Single-pass fp16.
// Output byte: bits 0-2 ctx index, bits 3-5 per-score rescue flags.
__global__ __launch_bounds__(256, 1)
void gemm_ctx(const __half* __restrict__ Ahi, const __half* __restrict__ Bhi,
              int K, int O,
              unsigned char* __restrict__ ctxout, const float* __restrict__ T)
{
    extern __shared__ char smraw[];
    const uint32_t smb = smem_u32(smraw);
    const int tid  = threadIdx.x;
    const int lane = tid & 31;
    const int wid  = tid >> 5;
    const int wm   = wid & 3;
    const int wn   = wid >> 2;
    const int row0 = blockIdx.x * 128;
    const int col0 = blockIdx.y * 192;

    const __half* gA = Ahi + (size_t)row0 * K;
    const __half* gB = Bhi + (size_t)col0 * K;

    float acc[2][12][4];
#pragma unroll
    for (int i = 0; i < 2; i++)
#pragma unroll
        for (int j = 0; j < 12; j++)
#pragma unroll
            for (int q = 0; q < 4; q++) acc[i][j][q] = 0.0f;

    const int nk = K >> 5;

    auto issue = [&](int s) {
        uint32_t base = smb + (uint32_t)(s & (CSTAGES - 1)) * C_STAGE;
        int k0 = s * 32;
#pragma unroll
        for (int t = 0; t < 2; t++) {           // A: 512 cp16
            int id = tid + t * 256;
            int r  = id >> 2, c = id & 3;
            cp16(base + r * PITCH + c * 16, gA + (size_t)r * K + k0 + c * 8);
        }
#pragma unroll
        for (int t = 0; t < 3; t++) {           // B: 768 cp16
            int id = tid + t * 256;
            int r  = id >> 2, c = id & 3;
            cp16(base + C_AB + r * PITCH + c * 16, gB + (size_t)r * K + k0 + c * 8);
        }
        CP_COMMIT();
    };

#pragma unroll
    for (int s = 0; s < CSTAGES - 1; s++) issue(s);

    const uint32_t lrow = (uint32_t)(lane & 15);
    const uint32_t lhal = (uint32_t)(lane >> 4) * 16;

    for (int it = 0; it < nk; it++) {
        asm volatile("cp.async.wait_group 2;" ::: "memory");
        __syncthreads();
        int pf = it + CSTAGES - 1;
        if (pf < nk) issue(pf); else CP_COMMIT();

        uint32_t stg = smb + (uint32_t)(it & (CSTAGES - 1)) * C_STAGE;
#pragma unroll
        for (int k16 = 0; k16 < 2; k16++) {
            uint32_t koff = lhal + (uint32_t)k16 * 32;
            uint32_t ah[2][4];
#pragma unroll
            for (int mi = 0; mi < 2; mi++) {
                uint32_t ro = (uint32_t)(wm * 32 + mi * 16) + lrow;
                ldsm4(ah[mi], stg + ro * PITCH + koff);
            }
            uint32_t bh[12][2];
#pragma unroll
            for (int jj = 0; jj < 6; jj++) {
                uint32_t ro = (uint32_t)(wn * 96 + jj * 16) + lrow;
                uint32_t r4[4];
                ldsm4(r4, stg + C_AB + ro * PITCH + koff);
                bh[jj * 2][0] = r4[0]; bh[jj * 2][1] = r4[2];
                bh[jj * 2 + 1][0] = r4[1]; bh[jj * 2 + 1][1] = r4[3];
            }
#pragma unroll
            for (int mi = 0; mi < 2; mi++)
#pragma unroll
                for (int nj = 0; nj < 12; nj++) hmma(acc[mi][nj], ah[mi], bh[nj]);
        }
    }
    asm volatile("cp.async.wait_group 0;" ::: "memory");
    __syncthreads();

    // ---- stage scores into smem ----
    float* ssc = (float*)smraw;
    const int rr = lane >> 2;
    const int q2 = (lane & 3) * 2;
#pragma unroll
    for (int mi = 0; mi < 2; mi++) {
        int r_lo = wm * 32 + mi * 16 + rr;
        int r_hi = r_lo + 8;
#pragma unroll
        for (int nj = 0; nj < 12; nj++) {
            int c = wn * 96 + nj * 8 + q2;
            *(float2*)&ssc[r_lo * SC_PITCH + c] = make_float2(acc[mi][nj][0], acc[mi][nj][1]);
            *(float2*)&ssc[r_hi * SC_PITCH + c] = make_float2(acc[mi][nj][2], acc[mi][nj][3]);
        }
    }
    __syncthreads();

    // ---- combine: 128 rows x 64 o-groups -> 2048 uint32 words ----
    const int oc0 = col0 / 3;
#pragma unroll
    for (int w8 = 0; w8 < 8; w8++) {
        int word_id = tid + w8 * 256;
        int r  = word_id >> 4;
        int wo = word_id & 15;
        const float* sp = ssc + r * SC_PITCH + wo * 12;
        uint32_t word = 0;
#pragma unroll
        for (int j = 0; j < 4; j++) {
            int o = oc0 + wo * 4 + j;
            int c = 0;
#pragma unroll
            for (int s = 0; s < 3; s++) {
                float th = __ldg(T + o * 3 + s);
                float d  = sp[j * 3 + s] - th;
                c |= ((int)(d > 0.0f)) << s;
                c |= ((int)(fabsf(d) < RESCUE_TAU)) << (3 + s);
            }
            word |= (uint32_t)((unsigned char)c) << (j * 8);
        }
        *(uint32_t*)(ctxout + (size_t)(row0 + r) * O + oc0 + wo * 4) = word;
    }
}

// ============================ warp-cooperative fp64 rescue =================
// Per-score flags (bits 3-5). Recompute only flagged scores; clear flags.
__global__ void gln_rescue(unsigned char* __restrict__ ctx,
                           const float* __restrict__ z,
                           const float* __restrict__ H,
                           const float* __restrict__ T,
                           int total4, int O, int K)
{
    int i    = blockIdx.x * blockDim.x + threadIdx.x;
    int lane = threadIdx.x & 31;
    uint32_t w = (i < total4) ? ((const uint32_t*)ctx)[i] : 0u;
    unsigned m = __ballot_sync(0xFFFFFFFFu, (w & 0x38383838u) != 0u);
    while (m) {
        int src = __ffs(m) - 1; m &= m - 1;
        uint32_t sw = __shfl_sync(0xFFFFFFFFu, w, src);
        int si = __shfl_sync(0xFFFFFFFFu, i, src);
#pragma unroll
        for (int j = 0; j < 4; j++) {
            uint32_t byte = (sw >> (j * 8)) & 0xFF;
            if (!(byte & 0x38)) continue;
            int idx = si * 4 + j;
            int b = idx / O, o = idx - b * O;
            const float* zr = z + (size_t)b * K;
            int c = (int)(byte & 7);
#pragma unroll
            for (int s = 0; s < 3; s++) {
                if (!(byte & (8u << s))) continue;
                const float* hr = H + (size_t)(o * 3 + s) * K;
                double p0 = 0.0, p1 = 0.0;           // 2 chains break DFMA latency
                for (int k = lane; k < K; k += 64) {
                    p0 += (double)zr[k]      * (double)hr[k];
                    p1 += (double)zr[k + 32] * (double)hr[k + 32];
                }
                double part = p0 + p1;
#pragma unroll
                for (int off = 16; off; off >>= 1)
                    part += __shfl_down_sync(0xFFFFFFFFu, part, off);
                part = __shfl_sync(0xFFFFFFFFu, part, 0);
                c = (c & ~(1 << s)) | (((int)(part > (double)T[o * 3 + s])) << s);
            }
            if (lane == 0) ctx[idx] = (unsigned char)c;
        }
    }
}

// ============================ select GEMM ==================================
// CTA 128x128, 8 warps (4Mx2N), warp 32x64. Single-pass fp16.
// MODE 1: hidden -> fp16.  MODE 2: final -> fp32.
template <int MODE>
__global__ __launch_bounds__(256, 1)
void gemm_sel(const __half* __restrict__ Ahi, const __half* __restrict__ Bhi,
              int K, int O,
              const unsigned char* __restrict__ ctx, const float* __restrict__ bias,
              float* __restrict__ outf, __half* __restrict__ outh)
{
    extern __shared__ char smraw[];
    const uint32_t smb = smem_u32(smraw);
    const int tid  = threadIdx.x;
    const int lane = tid & 31;
    const int wid  = tid >> 5;
    const int wm   = wid & 3;
    const int wn   = wid >> 2;
    const int row0 = blockIdx.x * 128;
    const int col0 = blockIdx.y * 128;

    const __half* gA = Ahi + (size_t)row0 * K;
    const __half* gB = Bhi + (size_t)col0 * K;

    float acc[2][8][4];
#pragma unroll
    for (int i = 0; i < 2; i++)
#pragma unroll
        for (int j = 0; j < 8; j++)
#pragma unroll
            for (int q = 0; q < 4; q++) acc[i][j][q] = 0.0f;

    const int nk = K >> 5;

    auto issue = [&](int s) {
        uint32_t base = smb + (uint32_t)(s & (SSTAGES - 1)) * S_STAGE;
        int k0 = s * 32;
#pragma unroll
        for (int t = 0; t < 4; t++) {           // 1024 cp16
            int id   = tid + t * 256;
            int tile = id >> 9;                 // 0..1
            int r    = (id >> 2) & 127;
            int c    = id & 3;
            const __half* g = tile ? gB : gA;
            cp16(base + tile * S_TILE + r * PITCH + c * 16,
                 g + (size_t)r * K + k0 + c * 8);
        }
        CP_COMMIT();
    };

#pragma unroll
    for (int s = 0; s < SSTAGES - 1; s++) issue(s);

    const uint32_t lrow = (uint32_t)(lane & 15);
    const uint32_t lhal = (uint32_t)(lane >> 4) * 16;

    for (int it = 0; it < nk; it++) {
        asm volatile("cp.async.wait_group 2;" ::: "memory");
        __syncthreads();
        int pf = it + SSTAGES - 1;
        if (pf < nk) issue(pf); else CP_COMMIT();

        uint32_t stg = smb + (uint32_t)(it & (SSTAGES - 1)) * S_STAGE;
#pragma unroll
        for (int k16 = 0; k16 < 2; k16++) {
            uint32_t koff = lhal + (uint32_t)k16 * 32;
            uint32_t ah[2][4];
#pragma unroll
            for (int mi = 0; mi < 2; mi++) {
                uint32_t ro = (uint32_t)(wm * 32 + mi * 16) + lrow;
                ldsm4(ah[mi], stg + ro * PITCH + koff);
            }
            uint32_t bh[8][2];
#pragma unroll
            for (int jj = 0; jj < 4; jj++) {
                uint32_t ro = (uint32_t)(wn * 64 + jj * 16) + lrow;
                uint32_t r4[4];
                ldsm4(r4, stg + S_TILE + ro * PITCH + koff);
                bh[jj * 2][0] = r4[0]; bh[jj * 2][1] = r4[2];
                bh[jj * 2 + 1][0] = r4[1]; bh[jj * 2 + 1][1] = r4[3];
            }
#pragma unroll
            for (int mi = 0; mi < 2; mi++)
#pragma unroll
                for (int nj = 0; nj < 8; nj++) hmma(acc[mi][nj], ah[mi], bh[nj]);
        }
    }

    // ---- 1-of-8 select epilogue ----
    const int rr = lane >> 2;
    const int q2 = (lane & 3) * 2;
#pragma unroll
    for (int mi = 0; mi < 2; mi++) {
        int r_lo = row0 + wm * 32 + mi * 16 + rr;
        int r_hi = r_lo + 8;
#pragma unroll
        for (int nj = 0; nj < 8; nj++) {
            int o   = (col0 + wn * 64 + nj * 8) >> 3;
            int cb0 = ctx[(size_t)r_lo * O + o] & 7;
            int cb1 = ctx[(size_t)r_hi * O + o] & 7;
            if (cb0 == q2 || cb0 == q2 + 1) {
                float v = (cb0 == q2) ? acc[mi][nj][0] : acc[mi][nj][1];
                if (bias) v += bias[o * 8 + cb0];
                size_t idx = (size_t)r_lo * O + o;
                if (MODE == 1) outh[idx] = __float2half_rn(v);
                else           outf[idx] = v;
            }
            if (cb1 == q2 || cb1 == q2 + 1) {
                float v = (cb1 == q2) ? acc[mi][nj][2] : acc[mi][nj][3];
                if (bias) v += bias[o * 8 + cb1];
                size_t idx = (size_t)r_hi * O + o;
                if (MODE == 1) outh[idx] = __float2half_rn(v);
                else           outf[idx] = v;
            }
        }
    }
}

// ============================ host =========================================
extern "C" void kernel_launch(void* const* d_in, const int* in_sizes, int n_in,
                              void* d_out, int out_size)
{
    const float* x  = (const float*)d_in[0];
    const float* W0 = (const float*)d_in[1];
    const float* W1 = (const float*)d_in[2];
    const float* W2 = (const float*)d_in[3];
    const float* b1 = (const float*)d_in[4];
    const float* b2 = (const float*)d_in[5];
    const float* H0 = (const float*)d_in[6];
    const float* T0 = (const float*)d_in[7];
    const float* H1 = (const float*)d_in[8];
    const float* T1 = (const float*)d_in[9];
    const float* H2 = (const float*)d_in[10];
    const float* T2 = (const float*)d_in[11];
    float* out = (float*)d_out;

    void *pxh, *pa, *pb, *pwa, *pwb, *pc0, *pc1, *pc2;
    cudaGetSymbolAddress(&pxh, g_xh);
    cudaGetSymbolAddress(&pa,  g_hA);  cudaGetSymbolAddress(&pb,  g_hB);
    cudaGetSymbolAddress(&pwa, g_whA); cudaGetSymbolAddress(&pwb, g_whB);
    cudaGetSymbolAddress(&pc0, g_ctx0); cudaGetSymbolAddress(&pc1, g_ctx1);
    cudaGetSymbolAddress(&pc2, g_ctx2);
    __half* xh  = (__half*)pxh;
    __half* hA  = (__half*)pa;   __half* hB  = (__half*)pb;
    __half* whA = (__half*)pwa;  __half* whB = (__half*)pwb;
    unsigned char* c0 = (unsigned char*)pc0;
    unsigned char* c1 = (unsigned char*)pc1;
    unsigned char* c2 = (unsigned char*)pc2;

    const int B = 4096, DIN = 1024, DLAT = 2048, DOUT = 1024;

    cudaFuncSetAttribute(gemm_ctx,    cudaFuncAttributeMaxDynamicSharedMemorySize, C_SMEM);
    cudaFuncSetAttribute(gemm_sel<1>, cudaFuncAttributeMaxDynamicSharedMemorySize, S_SMEM);
    cudaFuncSetAttribute(gemm_sel<2>, cudaFuncAttributeMaxDynamicSharedMemorySize, S_SMEM);

    auto conv = [](const float* in, __half* dst, size_t n) {
        int n4 = (int)(n / 4);
        conv_hi<<<(n4 + 255) / 256, 256>>>(in, dst, n4);
    };

    // Launch order arranged so the profiled launch (0-based #3) is gemm_ctx.
    conv(x,  xh,  (size_t)B * DIN);                                  // 0
    conv(H0, whA, (size_t)DLAT * 3 * DIN);                           // 1
    conv(W0, whB, (size_t)DLAT * 8 * DIN);                           // 2
    gemm_ctx<<<dim3(B / 128, (DLAT * 3) / 192), 256, C_SMEM>>>(      // 3
        xh, whA, DIN, DLAT, c0, T0);
    gln_rescue<<<(B * DLAT / 4 + 255) / 256, 256>>>(                 // 4
        c0, x, H0, T0, B * DLAT / 4, DLAT, DIN);
    gemm_sel<1><<<dim3(B / 128, (DLAT * 8) / 128), 256, S_SMEM>>>(   // 5
        xh, whB, DIN, DLAT, c0, nullptr, nullptr, hA);

    conv(H1, whA, (size_t)DLAT * 3 * DIN);                           // 6
    gemm_ctx<<<dim3(B / 128, (DLAT * 3) / 192), 256, C_SMEM>>>(      // 7
        xh, whA, DIN, DLAT, c1, T1);
    gln_rescue<<<(B * DLAT / 4 + 255) / 256, 256>>>(                 // 8
        c1, x, H1, T1, B * DLAT / 4, DLAT, DIN);
    conv(W1, whB, (size_t)DLAT * 8 * DLAT);                          // 9
    gemm_sel<1><<<dim3(B / 128, (DLAT * 8) / 128), 256, S_SMEM>>>(   // 10
        hA, whB, DLAT, DLAT, c1, b1, nullptr, hB);

    conv(H2, whA, (size_t)DOUT * 3 * DIN);                           // 11
    gemm_ctx<<<dim3(B / 128, (DOUT * 3) / 192), 256, C_SMEM>>>(      // 12
        xh, whA, DIN, DOUT, c2, T2);
    gln_rescue<<<(B * DOUT / 4 + 255) / 256, 256>>>(                 // 13
        c2, x, H2, T2, B * DOUT / 4, DOUT, DIN);
    conv(W2, whB, (size_t)DOUT * 8 * DLAT);                          // 14
    gemm_sel<2><<<dim3(B / 128, (DOUT * 8) / 128), 256, S_SMEM>>>(   // 15
        hB, whB, DLAT, DOUT, c2, b2, out, nullptr);

    (void)in_sizes; (void)n_in; (void)out_size;
}